// round 3
// baseline (speedup 1.0000x reference)
#include <cuda_runtime.h>

#define NN   1024
#define BB   32
#define NBIN 1024

// Intermediate layer-1 output: (B, N, 6)
__device__ float g_h[BB * NN * 6];

#define FPSCALE   0x1p40f
#define FPISCALE  0x1p-40f

// ---- inclusive block scan over 1024 elements (1 per thread), NA arrays ----
template<int NA>
__device__ __forceinline__ void blockScanIncl(float* v, float (*wsum)[32], int tid) {
    const int lane = tid & 31, wid = tid >> 5;
#pragma unroll
    for (int a = 0; a < NA; a++) {
#pragma unroll
        for (int d = 1; d < 32; d <<= 1) {
            float n = __shfl_up_sync(0xffffffffu, v[a], d);
            if (lane >= d) v[a] += n;
        }
        if (lane == 31) wsum[a][wid] = v[a];
    }
    __syncthreads();
    if (wid == 0) {
#pragma unroll
        for (int a = 0; a < NA; a++) {
            float w = wsum[a][lane];
#pragma unroll
            for (int d = 1; d < 32; d <<= 1) {
                float n = __shfl_up_sync(0xffffffffu, w, d);
                if (lane >= d) w += n;
            }
            wsum[a][lane] = w;
        }
    }
    __syncthreads();
    if (wid > 0) {
#pragma unroll
        for (int a = 0; a < NA; a++) v[a] += wsum[a][wid - 1];
    }
}

// ---- block min/max of one float, 1024 threads. s must hold 64 floats. ----
__device__ __forceinline__ float2 blockMinMax(float v, float* s, int tid) {
    const int lane = tid & 31, wid = tid >> 5;
    float mx = v, mn = v;
#pragma unroll
    for (int d = 16; d >= 1; d >>= 1) {
        mx = fmaxf(mx, __shfl_xor_sync(0xffffffffu, mx, d));
        mn = fminf(mn, __shfl_xor_sync(0xffffffffu, mn, d));
    }
    if (lane == 0) { s[wid] = mx; s[32 + wid] = mn; }
    __syncthreads();
    if (wid == 0) {
        mx = s[lane];
        mn = s[32 + lane];
#pragma unroll
        for (int d = 16; d >= 1; d >>= 1) {
            mx = fmaxf(mx, __shfl_xor_sync(0xffffffffu, mx, d));
            mn = fminf(mn, __shfl_xor_sync(0xffffffffu, mn, d));
        }
        if (lane == 0) { s[0] = mx; s[32] = mn; }
    }
    __syncthreads();
    float2 r = make_float2(s[32], s[0]);  // (min, max)
    __syncthreads();
    return r;
}

__device__ __forceinline__ unsigned long long fp64enc(float v) {
    return (unsigned long long)(long long)(v * FPSCALE);
}
__device__ __forceinline__ float fp64dec(unsigned long long u) {
    return __ll2float_rn((long long)u) * FPISCALE;
}

// ---------------------------------------------------------------------------
// Layer 1: H=3, F=4, O=2.  One block per (head, batch). 1024 threads.
// ---------------------------------------------------------------------------
__global__ void __launch_bounds__(1024, 1) gat1_kernel(
    const float* __restrict__ x,    // (B, N, 4)
    const float* __restrict__ W1,   // (3, 4, 2)
    const float* __restrict__ a1)   // (3, 4, 1)
{
    __shared__ unsigned long long bins[3][NBIN];   // 24 KB (also reused as float)
    __shared__ float wsum[3][32];
    __shared__ float redbuf[64];
    float* fb = reinterpret_cast<float*>(bins);

    const int hd  = blockIdx.x;
    const int b   = blockIdx.y;
    const int tid = threadIdx.x;

    float w[8];
#pragma unroll
    for (int i = 0; i < 8; i++) w[i] = W1[hd * 8 + i];
    const float as0 = a1[hd * 4 + 0], as1 = a1[hd * 4 + 1];
    const float ad0 = a1[hd * 4 + 2], ad1 = a1[hd * 4 + 3];

    float4 xv = reinterpret_cast<const float4*>(x)[b * NN + tid];
    const float wh0 = xv.x * w[0] + xv.y * w[2] + xv.z * w[4] + xv.w * w[6];
    const float wh1 = xv.x * w[1] + xv.y * w[3] + xv.z * w[5] + xv.w * w[7];
    const float ss  = wh0 * as0 + wh1 * as1;
    const float sd  = wh0 * ad0 + wh1 * ad1;

    float2 mm = blockMinMax(sd, redbuf, tid);
    const float mn = mm.x, M = mm.y;
    const float range = M - mn;
    const float scale = (range > 1e-30f) ? ((float)NBIN / range) : 0.0f;

    const int bj = min((int)((sd - mn) * scale), NBIN - 1);

    const float u = ss + M;
    const float m = fmaxf(u, 0.2f * u);
    const float p = __expf(u - m);
    const float q = __expf(0.2f * u - m);
    const float t = -ss;
    const int bt = (int)fminf(fmaxf(floorf((t - mn) * scale), -1.0f), (float)(NBIN - 1));

    const float A  = __expf(sd - M);
    const float Bv = __expf(0.2f * (sd - M));

    // ---- pass B: forward prefix over bins ----
#pragma unroll
    for (int a = 0; a < 3; a++) bins[a][tid] = 0ULL;
    __syncthreads();
    atomicAdd(&bins[0][bj], fp64enc(Bv));
    atomicAdd(&bins[1][bj], fp64enc(Bv * wh0));
    atomicAdd(&bins[2][bj], fp64enc(Bv * wh1));
    __syncthreads();
    float v[3];
#pragma unroll
    for (int a = 0; a < 3; a++) v[a] = fp64dec(bins[a][tid]);
    blockScanIncl<3>(v, wsum, tid);
#pragma unroll
    for (int a = 0; a < 3; a++) fb[a * NBIN + tid] = v[a];
    __syncthreads();
    float PB = 0.f, P0 = 0.f, P1 = 0.f;
    if (bt >= 0) { PB = fb[bt]; P0 = fb[NBIN + bt]; P1 = fb[2 * NBIN + bt]; }
    __syncthreads();

    // ---- pass A: reversed (suffix) over bins ----
#pragma unroll
    for (int a = 0; a < 3; a++) bins[a][tid] = 0ULL;
    __syncthreads();
    const int rb = NBIN - 1 - bj;
    atomicAdd(&bins[0][rb], fp64enc(A));
    atomicAdd(&bins[1][rb], fp64enc(A * wh0));
    atomicAdd(&bins[2][rb], fp64enc(A * wh1));
    __syncthreads();
#pragma unroll
    for (int a = 0; a < 3; a++) v[a] = fp64dec(bins[a][tid]);
    blockScanIncl<3>(v, wsum, tid);
#pragma unroll
    for (int a = 0; a < 3; a++) fb[a * NBIN + tid] = v[a];
    __syncthreads();
    float SA = 0.f, S0 = 0.f, S1 = 0.f;
    if (bt <= NBIN - 2) {
        int r = NBIN - 2 - bt;
        SA = fb[r]; S0 = fb[NBIN + r]; S1 = fb[2 * NBIN + r];
    }

    const float denom = q * PB + p * SA;
    const float inv = 1.0f / denom;
    float o0 = (q * P0 + p * S0) * inv;
    float o1 = (q * P1 + p * S1) * inv;
    o0 = (o0 > 0.f) ? o0 : expm1f(o0);
    o1 = (o1 > 0.f) ? o1 : expm1f(o1);

    float* dst = g_h + (size_t)(b * NN + tid) * 6 + hd * 2;
    dst[0] = o0;
    dst[1] = o1;
}

// ---------------------------------------------------------------------------
// Layer 2: H=1, F=6, O=4.  One block per batch. 1024 threads.
// ---------------------------------------------------------------------------
__global__ void __launch_bounds__(1024, 1) gat2_kernel(
    const float* __restrict__ W2,   // (1, 6, 4)
    const float* __restrict__ a2,   // (1, 8, 1)
    float* __restrict__ y)          // (B, N, 4)
{
    __shared__ unsigned long long bins[5][NBIN];   // 40 KB (also reused as float)
    __shared__ float wsum[5][32];
    __shared__ float redbuf[64];
    float* fb = reinterpret_cast<float*>(bins);

    const int b   = blockIdx.x;
    const int tid = threadIdx.x;

    float w[24];
#pragma unroll
    for (int i = 0; i < 24; i++) w[i] = W2[i];
    float asv[4], adv[4];
#pragma unroll
    for (int o = 0; o < 4; o++) { asv[o] = a2[o]; adv[o] = a2[4 + o]; }

    const float* hb = g_h + (size_t)(b * NN + tid) * 6;
    float2 h0 = *reinterpret_cast<const float2*>(hb);
    float2 h1 = *reinterpret_cast<const float2*>(hb + 2);
    float2 h2 = *reinterpret_cast<const float2*>(hb + 4);
    float xf[6] = {h0.x, h0.y, h1.x, h1.y, h2.x, h2.y};
    float wh[4];
#pragma unroll
    for (int o = 0; o < 4; o++) {
        float acc = 0.f;
#pragma unroll
        for (int f = 0; f < 6; f++) acc = fmaf(xf[f], w[f * 4 + o], acc);
        wh[o] = acc;
    }
    float ss = 0.f, sd = 0.f;
#pragma unroll
    for (int o = 0; o < 4; o++) {
        ss = fmaf(wh[o], asv[o], ss);
        sd = fmaf(wh[o], adv[o], sd);
    }

    float2 mm = blockMinMax(sd, redbuf, tid);
    const float mn = mm.x, M = mm.y;
    const float range = M - mn;
    const float scale = (range > 1e-30f) ? ((float)NBIN / range) : 0.0f;

    const int bj = min((int)((sd - mn) * scale), NBIN - 1);

    const float u = ss + M;
    const float m = fmaxf(u, 0.2f * u);
    const float p = __expf(u - m);
    const float q = __expf(0.2f * u - m);
    const float t = -ss;
    const int bt = (int)fminf(fmaxf(floorf((t - mn) * scale), -1.0f), (float)(NBIN - 1));

    const float A  = __expf(sd - M);
    const float Bv = __expf(0.2f * (sd - M));

    // ---- pass B ----
#pragma unroll
    for (int a = 0; a < 5; a++) bins[a][tid] = 0ULL;
    __syncthreads();
    atomicAdd(&bins[0][bj], fp64enc(Bv));
    atomicAdd(&bins[1][bj], fp64enc(Bv * wh[0]));
    atomicAdd(&bins[2][bj], fp64enc(Bv * wh[1]));
    atomicAdd(&bins[3][bj], fp64enc(Bv * wh[2]));
    atomicAdd(&bins[4][bj], fp64enc(Bv * wh[3]));
    __syncthreads();
    float v[5];
#pragma unroll
    for (int a = 0; a < 5; a++) v[a] = fp64dec(bins[a][tid]);
    blockScanIncl<5>(v, wsum, tid);
#pragma unroll
    for (int a = 0; a < 5; a++) fb[a * NBIN + tid] = v[a];
    __syncthreads();
    float PB = 0.f, P0 = 0.f, P1 = 0.f, P2 = 0.f, P3 = 0.f;
    if (bt >= 0) {
        PB = fb[bt];
        P0 = fb[NBIN + bt];
        P1 = fb[2 * NBIN + bt];
        P2 = fb[3 * NBIN + bt];
        P3 = fb[4 * NBIN + bt];
    }
    __syncthreads();

    // ---- pass A (reversed) ----
#pragma unroll
    for (int a = 0; a < 5; a++) bins[a][tid] = 0ULL;
    __syncthreads();
    const int rb = NBIN - 1 - bj;
    atomicAdd(&bins[0][rb], fp64enc(A));
    atomicAdd(&bins[1][rb], fp64enc(A * wh[0]));
    atomicAdd(&bins[2][rb], fp64enc(A * wh[1]));
    atomicAdd(&bins[3][rb], fp64enc(A * wh[2]));
    atomicAdd(&bins[4][rb], fp64enc(A * wh[3]));
    __syncthreads();
#pragma unroll
    for (int a = 0; a < 5; a++) v[a] = fp64dec(bins[a][tid]);
    blockScanIncl<5>(v, wsum, tid);
#pragma unroll
    for (int a = 0; a < 5; a++) fb[a * NBIN + tid] = v[a];
    __syncthreads();
    float SA = 0.f, S0 = 0.f, S1 = 0.f, S2 = 0.f, S3 = 0.f;
    if (bt <= NBIN - 2) {
        int r = NBIN - 2 - bt;
        SA = fb[r];
        S0 = fb[NBIN + r];
        S1 = fb[2 * NBIN + r];
        S2 = fb[3 * NBIN + r];
        S3 = fb[4 * NBIN + r];
    }

    const float denom = q * PB + p * SA;
    const float inv = 1.0f / denom;
    float o0 = (q * P0 + p * S0) * inv;
    float o1 = (q * P1 + p * S1) * inv;
    float o2 = (q * P2 + p * S2) * inv;
    float o3 = (q * P3 + p * S3) * inv;
    o0 = (o0 > 0.f) ? o0 : expm1f(o0);
    o1 = (o1 > 0.f) ? o1 : expm1f(o1);
    o2 = (o2 > 0.f) ? o2 : expm1f(o2);
    o3 = (o3 > 0.f) ? o3 : expm1f(o3);

    reinterpret_cast<float4*>(y)[b * NN + tid] = make_float4(o0, o1, o2, o3);
}

extern "C" void kernel_launch(void* const* d_in, const int* in_sizes, int n_in,
                              void* d_out, int out_size)
{
    const float* x  = (const float*)d_in[0];
    const float* W1 = (const float*)d_in[1];
    const float* a1 = (const float*)d_in[2];
    const float* W2 = (const float*)d_in[3];
    const float* a2 = (const float*)d_in[4];
    float* y = (float*)d_out;

    gat1_kernel<<<dim3(3, BB), 1024>>>(x, W1, a1);
    gat2_kernel<<<BB, 1024>>>(W2, a2, y);
}

// round 4
// speedup vs baseline: 1.0639x; 1.0639x over previous
#include <cuda_runtime.h>

#define NN   1024
#define BB   32
#define NBIN 1024

#define FPSCALE   0x1p40f
#define FPISCALE  0x1p-40f

// Intermediate layer-1 output: (B, N, 6)
__device__ float g_h[BB * NN * 6];

__device__ __forceinline__ long long fpenc(float v) {
    return (long long)(v * FPSCALE);
}
__device__ __forceinline__ float fpdec(long long u) {
    return __ll2float_rn(u) * FPISCALE;
}

// ---- u32 inclusive block scan over 1024 elements (value v at index tid) ----
__device__ __forceinline__ unsigned scanInclU32(unsigned v, unsigned* ws, int tid) {
    const int lane = tid & 31, wid = tid >> 5;
#pragma unroll
    for (int d = 1; d < 32; d <<= 1) {
        unsigned n = __shfl_up_sync(0xffffffffu, v, d);
        if (lane >= d) v += n;
    }
    if (lane == 31) ws[wid] = v;
    __syncthreads();
    if (wid == 0) {
        unsigned w = ws[lane];
#pragma unroll
        for (int d = 1; d < 32; d <<= 1) {
            unsigned n = __shfl_up_sync(0xffffffffu, w, d);
            if (lane >= d) w += n;
        }
        ws[lane] = w;
    }
    __syncthreads();
    if (wid > 0) v += ws[wid - 1];
    return v;
}

// ---- s64 inclusive block scan, NA independent arrays ----
template<int NA>
__device__ __forceinline__ void scanInclS64(long long* v, long long (*ws)[32], int tid) {
    const int lane = tid & 31, wid = tid >> 5;
#pragma unroll
    for (int a = 0; a < NA; a++) {
#pragma unroll
        for (int d = 1; d < 32; d <<= 1) {
            long long n = __shfl_up_sync(0xffffffffu, v[a], d);
            if (lane >= d) v[a] += n;
        }
        if (lane == 31) ws[a][wid] = v[a];
    }
    __syncthreads();
    if (wid == 0) {
#pragma unroll
        for (int a = 0; a < NA; a++) {
            long long w = ws[a][lane];
#pragma unroll
            for (int d = 1; d < 32; d <<= 1) {
                long long n = __shfl_up_sync(0xffffffffu, w, d);
                if (lane >= d) w += n;
            }
            ws[a][lane] = w;
        }
    }
    __syncthreads();
    if (wid > 0) {
#pragma unroll
        for (int a = 0; a < NA; a++) v[a] += ws[a][wid - 1];
    }
}

// ---- block min/max of one float, 1024 threads. s must hold 64 floats. ----
__device__ __forceinline__ float2 blockMinMax(float v, float* s, int tid) {
    const int lane = tid & 31, wid = tid >> 5;
    float mx = v, mn = v;
#pragma unroll
    for (int d = 16; d >= 1; d >>= 1) {
        mx = fmaxf(mx, __shfl_xor_sync(0xffffffffu, mx, d));
        mn = fminf(mn, __shfl_xor_sync(0xffffffffu, mn, d));
    }
    if (lane == 0) { s[wid] = mx; s[32 + wid] = mn; }
    __syncthreads();
    if (wid == 0) {
        mx = s[lane];
        mn = s[32 + lane];
#pragma unroll
        for (int d = 16; d >= 1; d >>= 1) {
            mx = fmaxf(mx, __shfl_xor_sync(0xffffffffu, mx, d));
            mn = fminf(mn, __shfl_xor_sync(0xffffffffu, mn, d));
        }
        if (lane == 0) { s[0] = mx; s[32] = mn; }
    }
    __syncthreads();
    float2 r = make_float2(s[32], s[0]);  // (min, max)
    __syncthreads();
    return r;
}

// Shared-memory layout offsets (bytes), NA = number of scan arrays.
// [0, NA*NN*8)            : stage (s64 values, then in-place prefixes)
// [+0, +4096)             : cnt (u32 per bin)
// [+4096, +8192)          : cinc (u32 inclusive count prefix per bin)
// [+8192, +8192+NA*256)   : ws64
// [.., +128)              : ws32
// [.., +256)              : redbuf
#define SMEM1_BYTES (6*NN*8  + 8192 + 6*256  + 128 + 256)
#define SMEM2_BYTES (10*NN*8 + 8192 + 10*256 + 128 + 256)

// ---------------------------------------------------------------------------
// Layer 1: H=3, F=4, O=2.  One block per (head, batch). 1024 threads.
// Arrays: 0:B 1:B*wh0 2:B*wh1 3:A 4:A*wh0 5:A*wh1
// ---------------------------------------------------------------------------
__global__ void __launch_bounds__(1024, 1) gat1_kernel(
    const float* __restrict__ x,    // (B, N, 4)
    const float* __restrict__ W1,   // (3, 4, 2)
    const float* __restrict__ a1)   // (3, 4, 1)
{
    extern __shared__ unsigned char smraw[];
    long long (*stage)[NN] = reinterpret_cast<long long(*)[NN]>(smraw);
    unsigned* cnt   = reinterpret_cast<unsigned*>(smraw + 6 * NN * 8);
    unsigned* cinc  = cnt + NBIN;
    long long (*ws64)[32] = reinterpret_cast<long long(*)[32]>(cinc + NBIN);
    unsigned* ws32  = reinterpret_cast<unsigned*>(ws64 + 6);
    float* redbuf   = reinterpret_cast<float*>(ws32 + 32);

    const int hd  = blockIdx.x;
    const int b   = blockIdx.y;
    const int tid = threadIdx.x;

    cnt[tid] = 0u;

    float w[8];
#pragma unroll
    for (int i = 0; i < 8; i++) w[i] = W1[hd * 8 + i];
    const float as0 = a1[hd * 4 + 0], as1 = a1[hd * 4 + 1];
    const float ad0 = a1[hd * 4 + 2], ad1 = a1[hd * 4 + 3];

    float4 xv = reinterpret_cast<const float4*>(x)[b * NN + tid];
    const float wh0 = xv.x * w[0] + xv.y * w[2] + xv.z * w[4] + xv.w * w[6];
    const float wh1 = xv.x * w[1] + xv.y * w[3] + xv.z * w[5] + xv.w * w[7];
    const float ss  = wh0 * as0 + wh1 * as1;
    const float sd  = wh0 * ad0 + wh1 * ad1;

    __syncthreads();                 // cnt zeroed (blockMinMax also syncs, but order matters)
    float2 mm = blockMinMax(sd, redbuf, tid);
    const float mn = mm.x, M = mm.y;
    const float range = M - mn;
    const float scale = (range > 1e-30f) ? ((float)NBIN / range) : 0.0f;

    const int bj = min((int)((sd - mn) * scale), NBIN - 1);
    const unsigned ticket = atomicAdd(&cnt[bj], 1u);
    __syncthreads();

    unsigned ci = scanInclU32(cnt[tid], ws32, tid);
    cinc[tid] = ci;
    __syncthreads();

    const unsigned pos = cinc[bj] - cnt[bj] + ticket;

    const float A  = __expf(sd - M);
    const float Bv = __expf(0.2f * (sd - M));
    stage[0][pos] = fpenc(Bv);
    stage[1][pos] = fpenc(Bv * wh0);
    stage[2][pos] = fpenc(Bv * wh1);
    stage[3][pos] = fpenc(A);
    stage[4][pos] = fpenc(A * wh0);
    stage[5][pos] = fpenc(A * wh1);
    __syncthreads();

    long long v[6];
#pragma unroll
    for (int a = 0; a < 6; a++) v[a] = stage[a][tid];
    scanInclS64<6>(v, ws64, tid);    // internal syncs cover the loads above
#pragma unroll
    for (int a = 0; a < 6; a++) stage[a][tid] = v[a];
    __syncthreads();

    // ---- row phase: row i == tid ----
    const float u = ss + M;
    const float m = fmaxf(u, 0.2f * u);
    const float p = __expf(u - m);
    const float q = __expf(0.2f * u - m);
    const float t = -ss;
    const int bt = (t < mn) ? -1 : min((int)((t - mn) * scale), NBIN - 1);
    const unsigned post = (bt >= 0) ? cinc[bt] : 0u;

    long long P0 = 0, P1 = 0, P2 = 0, P3 = 0, P4 = 0, P5 = 0;
    if (post > 0) {
        P0 = stage[0][post - 1]; P1 = stage[1][post - 1]; P2 = stage[2][post - 1];
        P3 = stage[3][post - 1]; P4 = stage[4][post - 1]; P5 = stage[5][post - 1];
    }
    const long long T3 = stage[3][NN - 1];
    const long long T4 = stage[4][NN - 1];
    const long long T5 = stage[5][NN - 1];

    const float denom = q * fpdec(P0) + p * fpdec(T3 - P3);
    const float inv = 1.0f / denom;
    float o0 = (q * fpdec(P1) + p * fpdec(T4 - P4)) * inv;
    float o1 = (q * fpdec(P2) + p * fpdec(T5 - P5)) * inv;
    o0 = (o0 > 0.f) ? o0 : expm1f(o0);
    o1 = (o1 > 0.f) ? o1 : expm1f(o1);

    float* dst = g_h + (size_t)(b * NN + tid) * 6 + hd * 2;
    dst[0] = o0;
    dst[1] = o1;
}

// ---------------------------------------------------------------------------
// Layer 2: H=1, F=6, O=4.  One block per batch. 1024 threads.
// Arrays: 0:B 1..4:B*wh  5:A 6..9:A*wh
// ---------------------------------------------------------------------------
__global__ void __launch_bounds__(1024, 1) gat2_kernel(
    const float* __restrict__ W2,   // (1, 6, 4)
    const float* __restrict__ a2,   // (1, 8, 1)
    float* __restrict__ y)          // (B, N, 4)
{
    extern __shared__ unsigned char smraw[];
    long long (*stage)[NN] = reinterpret_cast<long long(*)[NN]>(smraw);
    unsigned* cnt   = reinterpret_cast<unsigned*>(smraw + 10 * NN * 8);
    unsigned* cinc  = cnt + NBIN;
    long long (*ws64)[32] = reinterpret_cast<long long(*)[32]>(cinc + NBIN);
    unsigned* ws32  = reinterpret_cast<unsigned*>(ws64 + 10);
    float* redbuf   = reinterpret_cast<float*>(ws32 + 32);

    const int b   = blockIdx.x;
    const int tid = threadIdx.x;

    cnt[tid] = 0u;

    float w[24];
#pragma unroll
    for (int i = 0; i < 24; i++) w[i] = W2[i];
    float asv[4], adv[4];
#pragma unroll
    for (int o = 0; o < 4; o++) { asv[o] = a2[o]; adv[o] = a2[4 + o]; }

    const float* hb = g_h + (size_t)(b * NN + tid) * 6;
    float2 h0 = *reinterpret_cast<const float2*>(hb);
    float2 h1 = *reinterpret_cast<const float2*>(hb + 2);
    float2 h2 = *reinterpret_cast<const float2*>(hb + 4);
    float xf[6] = {h0.x, h0.y, h1.x, h1.y, h2.x, h2.y};
    float wh[4];
#pragma unroll
    for (int o = 0; o < 4; o++) {
        float acc = 0.f;
#pragma unroll
        for (int f = 0; f < 6; f++) acc = fmaf(xf[f], w[f * 4 + o], acc);
        wh[o] = acc;
    }
    float ss = 0.f, sd = 0.f;
#pragma unroll
    for (int o = 0; o < 4; o++) {
        ss = fmaf(wh[o], asv[o], ss);
        sd = fmaf(wh[o], adv[o], sd);
    }

    __syncthreads();                 // cnt zeroed
    float2 mm = blockMinMax(sd, redbuf, tid);
    const float mn = mm.x, M = mm.y;
    const float range = M - mn;
    const float scale = (range > 1e-30f) ? ((float)NBIN / range) : 0.0f;

    const int bj = min((int)((sd - mn) * scale), NBIN - 1);
    const unsigned ticket = atomicAdd(&cnt[bj], 1u);
    __syncthreads();

    unsigned ci = scanInclU32(cnt[tid], ws32, tid);
    cinc[tid] = ci;
    __syncthreads();

    const unsigned pos = cinc[bj] - cnt[bj] + ticket;

    const float A  = __expf(sd - M);
    const float Bv = __expf(0.2f * (sd - M));
    stage[0][pos] = fpenc(Bv);
    stage[1][pos] = fpenc(Bv * wh[0]);
    stage[2][pos] = fpenc(Bv * wh[1]);
    stage[3][pos] = fpenc(Bv * wh[2]);
    stage[4][pos] = fpenc(Bv * wh[3]);
    stage[5][pos] = fpenc(A);
    stage[6][pos] = fpenc(A * wh[0]);
    stage[7][pos] = fpenc(A * wh[1]);
    stage[8][pos] = fpenc(A * wh[2]);
    stage[9][pos] = fpenc(A * wh[3]);
    __syncthreads();

    long long v[10];
#pragma unroll
    for (int a = 0; a < 10; a++) v[a] = stage[a][tid];
    scanInclS64<10>(v, ws64, tid);
#pragma unroll
    for (int a = 0; a < 10; a++) stage[a][tid] = v[a];
    __syncthreads();

    // ---- row phase ----
    const float u = ss + M;
    const float m = fmaxf(u, 0.2f * u);
    const float p = __expf(u - m);
    const float q = __expf(0.2f * u - m);
    const float t = -ss;
    const int bt = (t < mn) ? -1 : min((int)((t - mn) * scale), NBIN - 1);
    const unsigned post = (bt >= 0) ? cinc[bt] : 0u;

    long long P[10];
#pragma unroll
    for (int a = 0; a < 10; a++) P[a] = 0;
    if (post > 0) {
#pragma unroll
        for (int a = 0; a < 10; a++) P[a] = stage[a][post - 1];
    }
    long long T[5];
#pragma unroll
    for (int a = 0; a < 5; a++) T[a] = stage[5 + a][NN - 1];

    const float denom = q * fpdec(P[0]) + p * fpdec(T[0] - P[5]);
    const float inv = 1.0f / denom;
    float o0 = (q * fpdec(P[1]) + p * fpdec(T[1] - P[6])) * inv;
    float o1 = (q * fpdec(P[2]) + p * fpdec(T[2] - P[7])) * inv;
    float o2 = (q * fpdec(P[3]) + p * fpdec(T[3] - P[8])) * inv;
    float o3 = (q * fpdec(P[4]) + p * fpdec(T[4] - P[9])) * inv;
    o0 = (o0 > 0.f) ? o0 : expm1f(o0);
    o1 = (o1 > 0.f) ? o1 : expm1f(o1);
    o2 = (o2 > 0.f) ? o2 : expm1f(o2);
    o3 = (o3 > 0.f) ? o3 : expm1f(o3);

    reinterpret_cast<float4*>(y)[b * NN + tid] = make_float4(o0, o1, o2, o3);
}

extern "C" void kernel_launch(void* const* d_in, const int* in_sizes, int n_in,
                              void* d_out, int out_size)
{
    const float* x  = (const float*)d_in[0];
    const float* W1 = (const float*)d_in[1];
    const float* a1 = (const float*)d_in[2];
    const float* W2 = (const float*)d_in[3];
    const float* a2 = (const float*)d_in[4];
    float* y = (float*)d_out;

    static int configured = 0;
    if (!configured) {
        cudaFuncSetAttribute(gat1_kernel, cudaFuncAttributeMaxDynamicSharedMemorySize, SMEM1_BYTES);
        cudaFuncSetAttribute(gat2_kernel, cudaFuncAttributeMaxDynamicSharedMemorySize, SMEM2_BYTES);
        configured = 1;
    }

    gat1_kernel<<<dim3(3, BB), 1024, SMEM1_BYTES>>>(x, W1, a1);
    gat2_kernel<<<BB, 1024, SMEM2_BYTES>>>(W2, a2, y);
}

// round 5
// speedup vs baseline: 1.0890x; 1.0236x over previous
#include <cuda_runtime.h>

#define NN   1024
#define BB   32
#define NBIN 1024

#define FPSCALE   0x1p40f
#define FPISCALE  0x1p-40f

// Intermediate layer-1 output: (B, N, 6)
__device__ float g_h[BB * NN * 6];

__device__ __forceinline__ long long fpenc(float v) { return (long long)(v * FPSCALE); }
__device__ __forceinline__ float     fpdec(long long u) { return __ll2float_rn(u) * FPISCALE; }

// bank-skew index: element i lives at i + i/32 (per-lane-contiguous chunks conflict-free)
__device__ __forceinline__ int IDX(int i) { return i + (i >> 5); }
#define PADN (NN + (NN >> 5))   // 1056

// ---- u32 inclusive block scan over 1024 values (one per thread) ----
__device__ __forceinline__ unsigned scanInclU32(unsigned v, unsigned* ws, int tid) {
    const int lane = tid & 31, wid = tid >> 5;
#pragma unroll
    for (int d = 1; d < 32; d <<= 1) {
        unsigned n = __shfl_up_sync(0xffffffffu, v, d);
        if (lane >= d) v += n;
    }
    if (lane == 31) ws[wid] = v;
    __syncthreads();
    if (wid == 0) {
        unsigned w = ws[lane];
#pragma unroll
        for (int d = 1; d < 32; d <<= 1) {
            unsigned n = __shfl_up_sync(0xffffffffu, w, d);
            if (lane >= d) w += n;
        }
        ws[lane] = w;
    }
    __syncthreads();
    if (wid > 0) v += ws[wid - 1];
    return v;
}

// ---- block min/max of one float, 1024 threads. s must hold 64 floats. ----
__device__ __forceinline__ float2 blockMinMax(float v, float* s, int tid) {
    const int lane = tid & 31, wid = tid >> 5;
    float mx = v, mn = v;
#pragma unroll
    for (int d = 16; d >= 1; d >>= 1) {
        mx = fmaxf(mx, __shfl_xor_sync(0xffffffffu, mx, d));
        mn = fminf(mn, __shfl_xor_sync(0xffffffffu, mn, d));
    }
    if (lane == 0) { s[wid] = mx; s[32 + wid] = mn; }
    __syncthreads();
    if (wid == 0) {
        mx = s[lane];
        mn = s[32 + lane];
#pragma unroll
        for (int d = 16; d >= 1; d >>= 1) {
            mx = fmaxf(mx, __shfl_xor_sync(0xffffffffu, mx, d));
            mn = fminf(mn, __shfl_xor_sync(0xffffffffu, mn, d));
        }
        if (lane == 0) { s[0] = mx; s[32] = mn; }
    }
    __syncthreads();
    float2 r = make_float2(s[32], s[0]);  // (min, max)
    __syncthreads();
    return r;
}

// ---- per-warp exact s64 prefix over 1024 elements of (e[], optionally *wm[]) ----
// lane handles contiguous chunk [lane*32, lane*32+32); results inclusive into tabrow.
__device__ __forceinline__ void warpScanArray(
    const float* __restrict__ e, const float* __restrict__ wm, bool usew,
    long long* __restrict__ tabrow, int lane)
{
    const int base = lane * 32;
    long long acc = 0;
#pragma unroll 8
    for (int k = 0; k < 32; k++) {
        int id = IDX(base + k);
        float v = e[id];
        if (usew) v *= wm[id];
        acc += fpenc(v);
    }
    long long tot = acc, s = acc;
#pragma unroll
    for (int d = 1; d < 32; d <<= 1) {
        long long n = __shfl_up_sync(0xffffffffu, s, d);
        if (lane >= d) s += n;
    }
    acc = s - tot;  // exclusive offset for this lane
#pragma unroll 8
    for (int k = 0; k < 32; k++) {
        int id = IDX(base + k);
        float v = e[id];
        if (usew) v *= wm[id];
        acc += fpenc(v);
        tabrow[id] = acc;
    }
}

// dynamic smem sizes
#define SMEM1_BYTES (4*PADN*4 + 6*PADN*8  + 4096 + 4096 + 128 + 256)
#define SMEM2_BYTES (6*PADN*4 + 10*PADN*8 + 4096 + 4096 + 128 + 256)

// ---------------------------------------------------------------------------
// Layer 1: H=3, F=4, O=2.  One block per (head, batch). 1024 threads.
// scat: 0:A 1:B 2:wh0 3:wh1.  tab: 0:B 1:B·wh0 2:B·wh1 3:A 4:A·wh0 5:A·wh1
// ---------------------------------------------------------------------------
__global__ void __launch_bounds__(1024, 1) gat1_kernel(
    const float* __restrict__ x,    // (B, N, 4)
    const float* __restrict__ W1,   // (3, 4, 2)
    const float* __restrict__ a1)   // (3, 4, 1)
{
    extern __shared__ unsigned char smraw[];
    float     (*scat)[PADN] = reinterpret_cast<float(*)[PADN]>(smraw);
    long long (*tab)[PADN]  = reinterpret_cast<long long(*)[PADN]>(smraw + 4 * PADN * 4);
    unsigned* cnt   = reinterpret_cast<unsigned*>(smraw + 4 * PADN * 4 + 6 * PADN * 8);
    unsigned* cinc  = cnt + NBIN;
    unsigned* ws32  = cinc + NBIN;
    float*    redbuf = reinterpret_cast<float*>(ws32 + 32);

    const int hd  = blockIdx.x;
    const int b   = blockIdx.y;
    const int tid = threadIdx.x;
    const int lane = tid & 31, wid = tid >> 5;

    cnt[tid] = 0u;

    float w[8];
#pragma unroll
    for (int i = 0; i < 8; i++) w[i] = W1[hd * 8 + i];
    const float as0 = a1[hd * 4 + 0], as1 = a1[hd * 4 + 1];
    const float ad0 = a1[hd * 4 + 2], ad1 = a1[hd * 4 + 3];

    float4 xv = reinterpret_cast<const float4*>(x)[b * NN + tid];
    const float wh0 = xv.x * w[0] + xv.y * w[2] + xv.z * w[4] + xv.w * w[6];
    const float wh1 = xv.x * w[1] + xv.y * w[3] + xv.z * w[5] + xv.w * w[7];
    const float ss  = wh0 * as0 + wh1 * as1;
    const float sd  = wh0 * ad0 + wh1 * ad1;

    float2 mm = blockMinMax(sd, redbuf, tid);   // internal syncs also cover cnt zeroing
    const float mn = mm.x, M = mm.y;
    const float range = M - mn;
    const float scale = (range > 1e-30f) ? ((float)NBIN / range) : 0.0f;

    const int bj = min((int)((sd - mn) * scale), NBIN - 1);
    const unsigned ticket = atomicAdd(&cnt[bj], 1u);
    __syncthreads();

    cinc[tid] = scanInclU32(cnt[tid], ws32, tid);
    __syncthreads();

    const int ip = IDX((int)(cinc[bj] - cnt[bj] + ticket));
    scat[0][ip] = __expf(sd - M);           // A
    scat[1][ip] = __expf(0.2f * (sd - M));  // B
    scat[2][ip] = wh0;
    scat[3][ip] = wh1;
    __syncthreads();

    if (wid < 6) {
        const int grp = wid / 3;            // 0 => B-group, 1 => A-group
        const int c   = wid % 3;
        warpScanArray(scat[grp == 0 ? 1 : 0],
                      scat[2 + (c ? c - 1 : 0)], c != 0,
                      tab[wid], lane);
    }
    __syncthreads();

    // ---- row phase: row i == tid ----
    const float u = ss + M;
    const float m = fmaxf(u, 0.2f * u);
    const float p = __expf(u - m);
    const float q = __expf(0.2f * u - m);
    const float t = -ss;
    const int bt = (t < mn) ? -1 : min((int)((t - mn) * scale), NBIN - 1);
    const unsigned post = (bt >= 0) ? cinc[bt] : 0u;

    long long P0 = 0, P1 = 0, P2 = 0, P3 = 0, P4 = 0, P5 = 0;
    if (post > 0) {
        const int ipq = IDX((int)post - 1);
        P0 = tab[0][ipq]; P1 = tab[1][ipq]; P2 = tab[2][ipq];
        P3 = tab[3][ipq]; P4 = tab[4][ipq]; P5 = tab[5][ipq];
    }
    const int il = IDX(NN - 1);
    const long long T3 = tab[3][il], T4 = tab[4][il], T5 = tab[5][il];

    const float denom = q * fpdec(P0) + p * fpdec(T3 - P3);
    const float inv = 1.0f / denom;
    float o0 = (q * fpdec(P1) + p * fpdec(T4 - P4)) * inv;
    float o1 = (q * fpdec(P2) + p * fpdec(T5 - P5)) * inv;
    o0 = (o0 > 0.f) ? o0 : expm1f(o0);
    o1 = (o1 > 0.f) ? o1 : expm1f(o1);

    float* dst = g_h + (size_t)(b * NN + tid) * 6 + hd * 2;
    dst[0] = o0;
    dst[1] = o1;
}

// ---------------------------------------------------------------------------
// Layer 2: H=1, F=6, O=4.  One block per batch. 1024 threads.
// scat: 0:A 1:B 2..5:wh0..3.  tab: 0:B 1..4:B·wh  5:A 6..9:A·wh
// ---------------------------------------------------------------------------
__global__ void __launch_bounds__(1024, 1) gat2_kernel(
    const float* __restrict__ W2,   // (1, 6, 4)
    const float* __restrict__ a2,   // (1, 8, 1)
    float* __restrict__ y)          // (B, N, 4)
{
    extern __shared__ unsigned char smraw[];
    float     (*scat)[PADN] = reinterpret_cast<float(*)[PADN]>(smraw);
    long long (*tab)[PADN]  = reinterpret_cast<long long(*)[PADN]>(smraw + 6 * PADN * 4);
    unsigned* cnt   = reinterpret_cast<unsigned*>(smraw + 6 * PADN * 4 + 10 * PADN * 8);
    unsigned* cinc  = cnt + NBIN;
    unsigned* ws32  = cinc + NBIN;
    float*    redbuf = reinterpret_cast<float*>(ws32 + 32);

    const int b   = blockIdx.x;
    const int tid = threadIdx.x;
    const int lane = tid & 31, wid = tid >> 5;

    cnt[tid] = 0u;

    float w[24];
#pragma unroll
    for (int i = 0; i < 24; i++) w[i] = W2[i];
    float asv[4], adv[4];
#pragma unroll
    for (int o = 0; o < 4; o++) { asv[o] = a2[o]; adv[o] = a2[4 + o]; }

    const float* hb = g_h + (size_t)(b * NN + tid) * 6;
    float2 h0 = *reinterpret_cast<const float2*>(hb);
    float2 h1 = *reinterpret_cast<const float2*>(hb + 2);
    float2 h2 = *reinterpret_cast<const float2*>(hb + 4);
    float xf[6] = {h0.x, h0.y, h1.x, h1.y, h2.x, h2.y};
    float wh[4];
#pragma unroll
    for (int o = 0; o < 4; o++) {
        float acc = 0.f;
#pragma unroll
        for (int f = 0; f < 6; f++) acc = fmaf(xf[f], w[f * 4 + o], acc);
        wh[o] = acc;
    }
    float ss = 0.f, sd = 0.f;
#pragma unroll
    for (int o = 0; o < 4; o++) {
        ss = fmaf(wh[o], asv[o], ss);
        sd = fmaf(wh[o], adv[o], sd);
    }

    float2 mm = blockMinMax(sd, redbuf, tid);
    const float mn = mm.x, M = mm.y;
    const float range = M - mn;
    const float scale = (range > 1e-30f) ? ((float)NBIN / range) : 0.0f;

    const int bj = min((int)((sd - mn) * scale), NBIN - 1);
    const unsigned ticket = atomicAdd(&cnt[bj], 1u);
    __syncthreads();

    cinc[tid] = scanInclU32(cnt[tid], ws32, tid);
    __syncthreads();

    const int ip = IDX((int)(cinc[bj] - cnt[bj] + ticket));
    scat[0][ip] = __expf(sd - M);           // A
    scat[1][ip] = __expf(0.2f * (sd - M));  // B
    scat[2][ip] = wh[0];
    scat[3][ip] = wh[1];
    scat[4][ip] = wh[2];
    scat[5][ip] = wh[3];
    __syncthreads();

    if (wid < 10) {
        const int grp = wid / 5;            // 0 => B-group, 1 => A-group
        const int c   = wid % 5;
        warpScanArray(scat[grp == 0 ? 1 : 0],
                      scat[2 + (c ? c - 1 : 0)], c != 0,
                      tab[wid], lane);
    }
    __syncthreads();

    // ---- row phase ----
    const float u = ss + M;
    const float m = fmaxf(u, 0.2f * u);
    const float p = __expf(u - m);
    const float q = __expf(0.2f * u - m);
    const float t = -ss;
    const int bt = (t < mn) ? -1 : min((int)((t - mn) * scale), NBIN - 1);
    const unsigned post = (bt >= 0) ? cinc[bt] : 0u;

    long long P[10];
#pragma unroll
    for (int a = 0; a < 10; a++) P[a] = 0;
    if (post > 0) {
        const int ipq = IDX((int)post - 1);
#pragma unroll
        for (int a = 0; a < 10; a++) P[a] = tab[a][ipq];
    }
    const int il = IDX(NN - 1);
    long long T[5];
#pragma unroll
    for (int a = 0; a < 5; a++) T[a] = tab[5 + a][il];

    const float denom = q * fpdec(P[0]) + p * fpdec(T[0] - P[5]);
    const float inv = 1.0f / denom;
    float o0 = (q * fpdec(P[1]) + p * fpdec(T[1] - P[6])) * inv;
    float o1 = (q * fpdec(P[2]) + p * fpdec(T[2] - P[7])) * inv;
    float o2 = (q * fpdec(P[3]) + p * fpdec(T[3] - P[8])) * inv;
    float o3 = (q * fpdec(P[4]) + p * fpdec(T[4] - P[9])) * inv;
    o0 = (o0 > 0.f) ? o0 : expm1f(o0);
    o1 = (o1 > 0.f) ? o1 : expm1f(o1);
    o2 = (o2 > 0.f) ? o2 : expm1f(o2);
    o3 = (o3 > 0.f) ? o3 : expm1f(o3);

    reinterpret_cast<float4*>(y)[b * NN + tid] = make_float4(o0, o1, o2, o3);
}

extern "C" void kernel_launch(void* const* d_in, const int* in_sizes, int n_in,
                              void* d_out, int out_size)
{
    const float* x  = (const float*)d_in[0];
    const float* W1 = (const float*)d_in[1];
    const float* a1 = (const float*)d_in[2];
    const float* W2 = (const float*)d_in[3];
    const float* a2 = (const float*)d_in[4];
    float* y = (float*)d_out;

    static int configured = 0;
    if (!configured) {
        cudaFuncSetAttribute(gat1_kernel, cudaFuncAttributeMaxDynamicSharedMemorySize, SMEM1_BYTES);
        cudaFuncSetAttribute(gat2_kernel, cudaFuncAttributeMaxDynamicSharedMemorySize, SMEM2_BYTES);
        configured = 1;
    }

    gat1_kernel<<<dim3(3, BB), 1024, SMEM1_BYTES>>>(x, W1, a1);
    gat2_kernel<<<BB, 1024, SMEM2_BYTES>>>(W2, a2, y);
}